// round 3
// baseline (speedup 1.0000x reference)
#include <cuda_runtime.h>
#include <math.h>

#define BB   32768
#define NN   27
#define HID  128
#define SINK_ITERS 20

// Staging buffer for transposed scores: [b][k][n] (pre-tau, pre-exp).
// Static __device__ array: allocation-free per harness rules.
__device__ float g_scores[(size_t)BB * NN * NN];

// ---------------- shared memory layout (floats) ----------------
#define OFF_W2   0          // 128*128 = 16384
#define OFF_W1   16384      // 4*128   = 512
#define OFF_B1   16896      // 128
#define OFF_B2   17024      // 128
#define OFF_G2   17152      // 128
#define OFF_BB2  17280      // 128
#define OFF_PROT 17408      // 27*129  = 3483  (stride 129 -> conflict-free lane-k reads)
#define OFF_A    20891      // 729
#define OFF_X    21620      // 27*4
#define OFF_R    21728      // 27*128  = 3456
#define OFF_H    25184      // 27*128  = 3456
#define OFF_SC   28640      // 27*29   = 783   ([k][n], stride 29)
#define OFF_LN1  29423      // 8 (g0..3, b0..3)
#define SMEM_FLOATS 29432
#define SMEM_BYTES  (SMEM_FLOATS * 4)

template<int R>
__device__ __forceinline__ void gemm_h_rows(const float* __restrict__ sr,
                                            const float4* __restrict__ W24,
                                            const float4 bbv,
                                            float4* __restrict__ sh4,
                                            int ng, int jq)
{
    float4 acc[R];
#pragma unroll
    for (int r = 0; r < R; r++) acc[r] = make_float4(0.f, 0.f, 0.f, 0.f);
#pragma unroll 4
    for (int i = 0; i < HID; i++) {
        float4 w = W24[i * 32 + jq];
#pragma unroll
        for (int r = 0; r < R; r++) {
            float rv = sr[(ng + 8 * r) * HID + i];   // warp-uniform broadcast
            acc[r].x = fmaf(rv, w.x, acc[r].x);
            acc[r].y = fmaf(rv, w.y, acc[r].y);
            acc[r].z = fmaf(rv, w.z, acc[r].z);
            acc[r].w = fmaf(rv, w.w, acc[r].w);
        }
    }
#pragma unroll
    for (int r = 0; r < R; r++) {
        float4 o;
        o.x = acc[r].x + bbv.x; o.y = acc[r].y + bbv.y;
        o.z = acc[r].z + bbv.z; o.w = acc[r].w + bbv.w;
        sh4[(ng + 8 * r) * 32 + jq] = o;
    }
}

__global__ void __launch_bounds__(256, 1)
k1_scores(const float* __restrict__ A,
          const float* __restrict__ m_,
          const float* __restrict__ ln1_g, const float* __restrict__ ln1_b,
          const float* __restrict__ W1,    const float* __restrict__ b1,
          const float* __restrict__ W2,    const float* __restrict__ b2,
          const float* __restrict__ ln2_g, const float* __restrict__ ln2_b,
          const float* __restrict__ protos)
{
    extern __shared__ float sm[];
    float* sW2  = sm + OFF_W2;
    float* sW1  = sm + OFF_W1;
    float* sb1  = sm + OFF_B1;
    float* sb2  = sm + OFF_B2;
    float* sg2  = sm + OFF_G2;
    float* sbb2 = sm + OFF_BB2;
    float* sP   = sm + OFF_PROT;
    float* sA   = sm + OFF_A;
    float* sx   = sm + OFF_X;
    float* sr   = sm + OFF_R;
    float* sh   = sm + OFF_H;
    float* ssc  = sm + OFF_SC;
    float* sln1 = sm + OFF_LN1;

    const int tid  = threadIdx.x;
    const int lane = tid & 31;
    const int warp = tid >> 5;

    // ---- one-time parameter staging ----
    for (int i = tid; i < HID * HID; i += 256) sW2[i] = W2[i];
    for (int i = tid; i < 4 * HID; i += 256)   sW1[i] = W1[i];
    if (tid < HID) {
        sb1[tid]  = b1[tid];
        sb2[tid]  = b2[tid];
        sg2[tid]  = ln2_g[tid];
        sbb2[tid] = ln2_b[tid];
    }
    for (int i = tid; i < NN * HID; i += 256)
        sP[(i >> 7) * 129 + (i & 127)] = protos[i];
    if (tid < 4) { sln1[tid] = ln1_g[tid]; sln1[4 + tid] = ln1_b[tid]; }
    __syncthreads();

    for (int b = blockIdx.x; b < BB; b += gridDim.x) {
        // ---- load A[b] tile (coalesced) ----
        const float* Ab = A + (size_t)b * (NN * NN);
        for (int i = tid; i < NN * NN; i += 256) sA[i] = Ab[i];
        __syncthreads();

        // ---- P1: features + LN1 (threads 0..26, one row each) ----
        if (tid < NN) {
            const int n = tid;
            float s = 0.f, t1 = 0.f, t2 = 0.f;   // entries >= 0; diag contributes 0
#pragma unroll
            for (int j = 0; j < NN; j++) {
                float a = sA[n * NN + j];
                s += a;
                float v = (j == n) ? 0.0f : a;
                if (v > t1) { t2 = t1; t1 = v; }
                else if (v > t2) { t2 = v; }
            }
            float f0 = log1pf(s);
            float f3 = m_[(size_t)b * NN + n];
            float mu = 0.25f * (f0 + t1 + t2 + f3);
            float d0 = f0 - mu, d1 = t1 - mu, d2 = t2 - mu, d3 = f3 - mu;
            float var = 0.25f * (d0 * d0 + d1 * d1 + d2 * d2 + d3 * d3);
            float rs = rsqrtf(var + 1e-5f);
            sx[n * 4 + 0] = d0 * rs * sln1[0] + sln1[4];
            sx[n * 4 + 1] = d1 * rs * sln1[1] + sln1[5];
            sx[n * 4 + 2] = d2 * rs * sln1[2] + sln1[6];
            sx[n * 4 + 3] = d3 * rs * sln1[3] + sln1[7];
        }
        __syncthreads();

        // ---- P2: u = x@W1 + b1, r = relu(u) ----
        for (int idx = tid; idx < NN * HID; idx += 256) {
            int n = idx >> 7, j = idx & 127;
            float u = sb1[j];
            u = fmaf(sx[n * 4 + 0], sW1[0 * HID + j], u);
            u = fmaf(sx[n * 4 + 1], sW1[1 * HID + j], u);
            u = fmaf(sx[n * 4 + 2], sW1[2 * HID + j], u);
            u = fmaf(sx[n * 4 + 3], sW1[3 * HID + j], u);
            sr[idx] = fmaxf(u, 0.f);
        }
        __syncthreads();

        // ---- P3: h = r @ W2 + b2  (dominant GEMM; 4-row register blocking) ----
        {
            const int jq = lane;      // 4-wide j group: j = 4*jq..4*jq+3
            const int ng = warp;      // base row; rows ng, ng+8, ng+16, (ng+24)
            const float4* W24 = (const float4*)sW2;
            float4* sh4 = (float4*)sh;
            float4 bbv = ((const float4*)sb2)[jq];
            if (ng < 3) gemm_h_rows<4>(sr, W24, bbv, sh4, ng, jq);
            else        gemm_h_rows<3>(sr, W24, bbv, sh4, ng, jq);
        }
        __syncthreads();

        // ---- P4: LayerNorm(128) per row, in place (warp per row) ----
        for (int n = warp; n < NN; n += 8) {
            float4 v = ((float4*)sh)[n * 32 + lane];
            float s  = v.x + v.y + v.z + v.w;
            float s2 = v.x * v.x + v.y * v.y + v.z * v.z + v.w * v.w;
#pragma unroll
            for (int off = 16; off >= 1; off >>= 1) {
                s  += __shfl_xor_sync(0xffffffffu, s,  off);
                s2 += __shfl_xor_sync(0xffffffffu, s2, off);
            }
            float mu  = s  * (1.f / 128.f);
            float var = s2 * (1.f / 128.f) - mu * mu;
            float rs  = rsqrtf(var + 1e-5f);
            float4 g  = ((const float4*)sg2)[lane];
            float4 be = ((const float4*)sbb2)[lane];
            float4 o;
            o.x = (v.x - mu) * rs * g.x + be.x;
            o.y = (v.y - mu) * rs * g.y + be.y;
            o.z = (v.z - mu) * rs * g.z + be.z;
            o.w = (v.w - mu) * rs * g.w + be.w;
            ((float4*)sh)[n * 32 + lane] = o;
        }
        __syncthreads();

        // ---- P5: scores[n][k] = H[n]·protos[k]; store transposed ssc[k][n] ----
        {
            const int k  = lane;
            const int n0 = warp;
            if (k < NN) {
                const float* Pk = sP + k * 129;      // stride 129 -> no bank conflicts
                const float* H0 = sh + n0 * HID;
                const float* H1 = H0 + 8 * HID;
                const float* H2 = H0 + 16 * HID;
                const float* H3 = H0 + 24 * HID;
                float a0 = 0.f, a1 = 0.f, a2 = 0.f, a3 = 0.f;
                const bool h3 = (n0 + 24) < NN;
                if (h3) {
#pragma unroll 4
                    for (int j = 0; j < HID; j++) {
                        float pv = Pk[j];
                        a0 = fmaf(H0[j], pv, a0);
                        a1 = fmaf(H1[j], pv, a1);
                        a2 = fmaf(H2[j], pv, a2);
                        a3 = fmaf(H3[j], pv, a3);
                    }
                } else {
#pragma unroll 4
                    for (int j = 0; j < HID; j++) {
                        float pv = Pk[j];
                        a0 = fmaf(H0[j], pv, a0);
                        a1 = fmaf(H1[j], pv, a1);
                        a2 = fmaf(H2[j], pv, a2);
                    }
                }
                ssc[k * 29 + n0]      = a0;
                ssc[k * 29 + n0 + 8]  = a1;
                ssc[k * 29 + n0 + 16] = a2;
                if (h3) ssc[k * 29 + n0 + 24] = a3;
            }
        }
        __syncthreads();

        // ---- write transposed scores to staging (coalesced) ----
        {
            float* dstb = g_scores + (size_t)b * (NN * NN);
            for (int i = tid; i < NN * NN; i += 256) {
                int k = i / NN;
                int n = i - k * NN;
                dstb[i] = ssc[k * 29 + n];
            }
        }
        __syncthreads();
    }
}

// ---------------- Sinkhorn: warp per batch, matrix in registers ----------------
// Lane = column n (lanes 27..31 hold zeros). p[k] = P[k][lane].
// Multiplicative domain (exactly equivalent to log-domain logsumexp updates).
__global__ void __launch_bounds__(256)
k2_sinkhorn(const float* __restrict__ tau_r, float* __restrict__ out)
{
    const int warp = threadIdx.x >> 5;
    const int lane = threadIdx.x & 31;
    const int b = blockIdx.x * 8 + warp;
    if (b >= BB) return;

    const float inv_tau = 1.0f / tau_r[0];
    const float* src = g_scores + (size_t)b * (NN * NN);

    float p[NN];
#pragma unroll
    for (int k = 0; k < NN; k++) {
        float v = (lane < NN) ? src[k * NN + lane] : 0.f;
        p[k] = (lane < NN) ? __expf(v * inv_tau) : 0.f;
    }

#pragma unroll 1
    for (int it = 0; it < SINK_ITERS; it++) {
        // row normalize: sum over n (across lanes); zeros in lanes>=27 are harmless
#pragma unroll
        for (int k = 0; k < NN; k++) {
            float s = p[k];
            s += __shfl_xor_sync(0xffffffffu, s, 16);
            s += __shfl_xor_sync(0xffffffffu, s, 8);
            s += __shfl_xor_sync(0xffffffffu, s, 4);
            s += __shfl_xor_sync(0xffffffffu, s, 2);
            s += __shfl_xor_sync(0xffffffffu, s, 1);
            p[k] *= __fdividef(1.f, s);
        }
        // column normalize: sum over k (in-lane)
        float c = 0.f;
#pragma unroll
        for (int k = 0; k < NN; k++) c += p[k];
        float ci = (lane < NN) ? __fdividef(1.f, c) : 0.f;  // keep dead lanes at 0
#pragma unroll
        for (int k = 0; k < NN; k++) p[k] *= ci;
    }

    float* dst = out + (size_t)b * (NN * NN);
    if (lane < NN) {
#pragma unroll
        for (int k = 0; k < NN; k++) dst[k * NN + lane] = p[k];
    }
}

extern "C" void kernel_launch(void* const* d_in, const int* in_sizes, int n_in,
                              void* d_out, int out_size)
{
    const float* A      = (const float*)d_in[0];
    const float* m_     = (const float*)d_in[1];
    const float* tau_r  = (const float*)d_in[2];
    const float* ln1_g  = (const float*)d_in[3];
    const float* ln1_b  = (const float*)d_in[4];
    const float* W1     = (const float*)d_in[5];
    const float* b1     = (const float*)d_in[6];
    const float* W2     = (const float*)d_in[7];
    const float* b2     = (const float*)d_in[8];
    const float* ln2_g  = (const float*)d_in[9];
    const float* ln2_b  = (const float*)d_in[10];
    const float* protos = (const float*)d_in[11];

    int smCount = 148;
    cudaDeviceGetAttribute(&smCount, cudaDevAttrMultiProcessorCount, 0);
    cudaFuncSetAttribute((const void*)k1_scores,
                         cudaFuncAttributeMaxDynamicSharedMemorySize, SMEM_BYTES);

    k1_scores<<<smCount, 256, SMEM_BYTES>>>(A, m_, ln1_g, ln1_b, W1, b1,
                                            W2, b2, ln2_g, ln2_b, protos);
    k2_sinkhorn<<<(BB + 7) / 8, 256>>>(tau_r, (float*)d_out);
}

// round 4
// speedup vs baseline: 1.2623x; 1.2623x over previous
#include <cuda_runtime.h>
#include <math.h>

#define BB   32768
#define NPAIR 16384
#define NN   27
#define HID  128
#define SINK_ITERS 20

// Staging buffer for transposed scores: [b][k][n] (pre-tau, pre-exp).
__device__ float g_scores[(size_t)BB * NN * NN];

// ---------------- shared memory layout (floats) ----------------
#define OFF_W2   0          // 128*128
#define OFF_W1   16384      // 4*128
#define OFF_B1   16896
#define OFF_B2   17024
#define OFF_G2   17152
#define OFF_BB2  17280
#define OFF_LN1  17408      // 8
#define OFF_M    17416      // 54 (pad 64)
#define OFF_P    17480      // 27*132 = 3564 ; stride 132 -> conflict-free LDS.128 spread
#define P_STRIDE 132
#define OFF_BAT  21044
// per-batch sub-offsets
#define BO_A 0               // 729 (pad 732)
#define BO_X 732              // 108 (pad 112)
#define BO_R 844              // 27*128
#define BO_H 4300             // 27*128
#define BO_SC 7756            // 27*29 = 783
#define PB   8540
#define SMEM_FLOATS (OFF_BAT + 2*PB)
#define SMEM_BYTES  (SMEM_FLOATS * 4)

// packed fp32x2 FMA (bit-exact IEEE fp32 per component)
#define FFMA2ACC(d,a,b) asm("fma.rn.f32x2 %0, %1, %2, %0;" : "+l"(d) : "l"(a), "l"(b))

__device__ __forceinline__ unsigned long long dup2(float x) {
    unsigned long long r;
    asm("mov.b64 %0, {%1, %2};" : "=l"(r) : "f"(x), "f"(x));
    return r;
}
__device__ __forceinline__ float2 unpk(unsigned long long v) {
    float2 f;
    asm("mov.b64 {%0, %1}, %2;" : "=f"(f.x), "=f"(f.y) : "l"(v));
    return f;
}

// ---- P3: h = relu_r @ W2 + b2, NR rows (n = w2 + 2t), lane jq owns j=4jq..4jq+3 ----
template<int NR>
__device__ __forceinline__ void p3_rows(const float* __restrict__ srb,
                                        float* __restrict__ shb,
                                        const float* __restrict__ sW2,
                                        const float* __restrict__ sb2,
                                        int w2, int jq)
{
    const ulonglong2* W2v = (const ulonglong2*)sW2;
    unsigned long long aL[NR], aH[NR];
#pragma unroll
    for (int t = 0; t < NR; t++) { aL[t] = 0ull; aH[t] = 0ull; }
#pragma unroll 1
    for (int i = 0; i < HID; i += 4) {
        ulonglong2 w0 = W2v[(i + 0) * 32 + jq];
        ulonglong2 w1 = W2v[(i + 1) * 32 + jq];
        ulonglong2 w2v = W2v[(i + 2) * 32 + jq];
        ulonglong2 w3 = W2v[(i + 3) * 32 + jq];
#pragma unroll
        for (int t = 0; t < NR; t++) {
            const int n = w2 + 2 * t;
            float4 rq = *(const float4*)(srb + n * HID + i);     // broadcast LDS.128
            unsigned long long r0 = dup2(rq.x), r1 = dup2(rq.y);
            unsigned long long r2 = dup2(rq.z), r3 = dup2(rq.w);
            FFMA2ACC(aL[t], r0, w0.x);  FFMA2ACC(aH[t], r0, w0.y);
            FFMA2ACC(aL[t], r1, w1.x);  FFMA2ACC(aH[t], r1, w1.y);
            FFMA2ACC(aL[t], r2, w2v.x); FFMA2ACC(aH[t], r2, w2v.y);
            FFMA2ACC(aL[t], r3, w3.x);  FFMA2ACC(aH[t], r3, w3.y);
        }
    }
    float4 bb = ((const float4*)sb2)[jq];
#pragma unroll
    for (int t = 0; t < NR; t++) {
        const int n = w2 + 2 * t;
        float2 lo = unpk(aL[t]), hi = unpk(aH[t]);
        float4 o;
        o.x = lo.x + bb.x; o.y = lo.y + bb.y;
        o.z = hi.x + bb.z; o.w = hi.y + bb.w;
        *(float4*)(shb + n * HID + 4 * jq) = o;
    }
}

// ---- P5: scores[n][k] = H[n]·protos[k], lane = k, NR rows; store ssc[k][n] ----
template<int NR>
__device__ __forceinline__ void p5_rows(const float* __restrict__ shb,
                                        const float* __restrict__ sP,
                                        float* __restrict__ ssc,
                                        int w2, int k, bool kvalid)
{
    const int kk = kvalid ? k : (NN - 1);
    const ulonglong2* Pv = (const ulonglong2*)sP;    // row stride 132 fl = 33 ull2
    unsigned long long acc[NR];
#pragma unroll
    for (int t = 0; t < NR; t++) acc[t] = 0ull;
#pragma unroll 1
    for (int jq = 0; jq < 32; jq++) {
        ulonglong2 pv = Pv[kk * 33 + jq];            // conflict-free spread LDS.128
#pragma unroll
        for (int t = 0; t < NR; t++) {
            const int n = w2 + 2 * t;
            ulonglong2 hv = *(const ulonglong2*)(shb + n * HID + 4 * jq);  // broadcast
            FFMA2ACC(acc[t], hv.x, pv.x);
            FFMA2ACC(acc[t], hv.y, pv.y);
        }
    }
    if (kvalid) {
#pragma unroll
        for (int t = 0; t < NR; t++) {
            float2 s = unpk(acc[t]);
            ssc[k * 29 + (w2 + 2 * t)] = s.x + s.y;
        }
    }
}

__global__ void __launch_bounds__(128, 1)
k1_scores(const float* __restrict__ A,
          const float* __restrict__ m_,
          const float* __restrict__ ln1_g, const float* __restrict__ ln1_b,
          const float* __restrict__ W1,    const float* __restrict__ b1,
          const float* __restrict__ W2,    const float* __restrict__ b2,
          const float* __restrict__ ln2_g, const float* __restrict__ ln2_b,
          const float* __restrict__ protos)
{
    extern __shared__ float sm[];
    const int tid  = threadIdx.x;
    const int lane = tid & 31;
    const int h    = tid >> 6;          // which batch of the pair
    const int htid = tid & 63;          // thread id within the 64-thread half
    const int w2   = (tid >> 5) & 1;    // warp within half: even/odd rows

    // ---- one-time parameter staging ----
    for (int i = tid; i < HID * HID; i += 128) sm[OFF_W2 + i] = W2[i];
    for (int i = tid; i < 4 * HID; i += 128)   sm[OFF_W1 + i] = W1[i];
    if (tid < HID) {
        sm[OFF_B1 + tid]  = b1[tid];
        sm[OFF_B2 + tid]  = b2[tid];
        sm[OFF_G2 + tid]  = ln2_g[tid];
        sm[OFF_BB2 + tid] = ln2_b[tid];
    }
    if (tid < 4) { sm[OFF_LN1 + tid] = ln1_g[tid]; sm[OFF_LN1 + 4 + tid] = ln1_b[tid]; }
    for (int i = tid; i < NN * HID; i += 128)
        sm[OFF_P + (i >> 7) * P_STRIDE + (i & 127)] = protos[i];
    __syncthreads();

    // ---- software pipeline: prefetch A/m for the current pair into registers ----
    float pf[12];
    float mreg = 0.f;
    int bp = blockIdx.x;
    {
        const float* src = A + (size_t)bp * (2 * NN * NN);
#pragma unroll
        for (int q = 0; q < 12; q++) {
            int idx = tid + 128 * q;
            pf[q] = (idx < 2 * NN * NN) ? src[idx] : 0.f;
        }
        if (tid < 2 * NN) mreg = m_[(size_t)bp * 2 * NN + tid];
    }

    for (; bp < NPAIR; bp += (int)gridDim.x) {
        float* sA0 = sm + OFF_BAT + BO_A;
        float* sA1 = sm + OFF_BAT + PB + BO_A;
#pragma unroll
        for (int q = 0; q < 12; q++) {
            int idx = tid + 128 * q;
            if (idx < NN * NN)          sA0[idx] = pf[q];
            else if (idx < 2 * NN * NN) sA1[idx - NN * NN] = pf[q];
        }
        if (tid < 2 * NN) sm[OFF_M + tid] = mreg;
        __syncthreads();

        // prefetch next pair while this one computes
        {
            int bpn = bp + (int)gridDim.x;
            if (bpn < NPAIR) {
                const float* src = A + (size_t)bpn * (2 * NN * NN);
#pragma unroll
                for (int q = 0; q < 12; q++) {
                    int idx = tid + 128 * q;
                    pf[q] = (idx < 2 * NN * NN) ? src[idx] : 0.f;
                }
                if (tid < 2 * NN) mreg = m_[(size_t)bpn * 2 * NN + tid];
            }
        }

        float* sB  = sm + OFF_BAT + h * PB;
        float* sA  = sB + BO_A;
        float* sx  = sB + BO_X;
        float* sr  = sB + BO_R;
        float* sh  = sB + BO_H;
        float* ssc = sB + BO_SC;

        // ---- P1: features + LN1 (27 threads per half) ----
        if (htid < NN) {
            const int n = htid;
            float s = 0.f, t1 = 0.f, t2 = 0.f;
#pragma unroll
            for (int j = 0; j < NN; j++) {
                float a = sA[n * NN + j];
                s += a;
                float v = (j == n) ? 0.0f : a;
                if (v > t1) { t2 = t1; t1 = v; }
                else if (v > t2) { t2 = v; }
            }
            float f0 = log1pf(s);
            float f3 = sm[OFF_M + h * NN + n];
            float mu = 0.25f * (f0 + t1 + t2 + f3);
            float d0 = f0 - mu, d1 = t1 - mu, d2 = t2 - mu, d3 = f3 - mu;
            float var = 0.25f * (d0 * d0 + d1 * d1 + d2 * d2 + d3 * d3);
            float rs = rsqrtf(var + 1e-5f);
            sx[n * 4 + 0] = d0 * rs * sm[OFF_LN1 + 0] + sm[OFF_LN1 + 4];
            sx[n * 4 + 1] = d1 * rs * sm[OFF_LN1 + 1] + sm[OFF_LN1 + 5];
            sx[n * 4 + 2] = d2 * rs * sm[OFF_LN1 + 2] + sm[OFF_LN1 + 6];
            sx[n * 4 + 3] = d3 * rs * sm[OFF_LN1 + 3] + sm[OFF_LN1 + 7];
        }
        __syncthreads();

        // ---- P2: r = relu(x @ W1 + b1) ----
        for (int idx = htid; idx < NN * HID; idx += 64) {
            int n = idx >> 7, j = idx & 127;
            float u = sm[OFF_B1 + j];
            u = fmaf(sx[n * 4 + 0], sm[OFF_W1 + 0 * HID + j], u);
            u = fmaf(sx[n * 4 + 1], sm[OFF_W1 + 1 * HID + j], u);
            u = fmaf(sx[n * 4 + 2], sm[OFF_W1 + 2 * HID + j], u);
            u = fmaf(sx[n * 4 + 3], sm[OFF_W1 + 3 * HID + j], u);
            sr[idx] = fmaxf(u, 0.f);
        }
        __syncthreads();

        // ---- P3: dominant GEMM in packed f32x2 ----
        if (w2 == 0) p3_rows<14>(sr, sh, sm + OFF_W2, sm + OFF_B2, 0, lane);
        else         p3_rows<13>(sr, sh, sm + OFF_W2, sm + OFF_B2, 1, lane);
        __syncthreads();

        // ---- P4: LayerNorm(128) per row (warp per row, even/odd split) ----
        for (int n = w2; n < NN; n += 2) {
            float4 v = ((float4*)sh)[n * 32 + lane];
            float s  = v.x + v.y + v.z + v.w;
            float s2 = v.x * v.x + v.y * v.y + v.z * v.z + v.w * v.w;
#pragma unroll
            for (int off = 16; off >= 1; off >>= 1) {
                s  += __shfl_xor_sync(0xffffffffu, s,  off);
                s2 += __shfl_xor_sync(0xffffffffu, s2, off);
            }
            float mu  = s  * (1.f / 128.f);
            float var = s2 * (1.f / 128.f) - mu * mu;
            float rs  = rsqrtf(var + 1e-5f);
            float4 g  = ((const float4*)(sm + OFF_G2))[lane];
            float4 be = ((const float4*)(sm + OFF_BB2))[lane];
            float4 o;
            o.x = (v.x - mu) * rs * g.x + be.x;
            o.y = (v.y - mu) * rs * g.y + be.y;
            o.z = (v.z - mu) * rs * g.z + be.z;
            o.w = (v.w - mu) * rs * g.w + be.w;
            ((float4*)sh)[n * 32 + lane] = o;
        }
        __syncthreads();

        // ---- P5: scores in packed f32x2, stored transposed [k][n] ----
        if (w2 == 0) p5_rows<14>(sh, sm + OFF_P, ssc, 0, lane, lane < NN);
        else         p5_rows<13>(sh, sm + OFF_P, ssc, 1, lane, lane < NN);
        __syncthreads();

        // ---- write transposed scores (coalesced) ----
        {
            float* dst = g_scores + (size_t)(2 * bp + h) * (NN * NN);
            for (int i = htid; i < NN * NN; i += 64) {
                int k = i / NN;
                int n = i - k * NN;
                dst[i] = ssc[k * 29 + n];
            }
        }
        __syncthreads();
    }
}

// ---------------- Sinkhorn: warp per batch, matrix in registers ----------------
__global__ void __launch_bounds__(256)
k2_sinkhorn(const float* __restrict__ tau_r, float* __restrict__ out)
{
    const int warp = threadIdx.x >> 5;
    const int lane = threadIdx.x & 31;
    const int b = blockIdx.x * 8 + warp;
    if (b >= BB) return;

    const float inv_tau = 1.0f / tau_r[0];
    const float* src = g_scores + (size_t)b * (NN * NN);

    float p[NN];
#pragma unroll
    for (int k = 0; k < NN; k++) {
        float v = (lane < NN) ? src[k * NN + lane] : 0.f;
        p[k] = (lane < NN) ? __expf(v * inv_tau) : 0.f;
    }

#pragma unroll 1
    for (int it = 0; it < SINK_ITERS; it++) {
#pragma unroll
        for (int k = 0; k < NN; k++) {
            float s = p[k];
            s += __shfl_xor_sync(0xffffffffu, s, 16);
            s += __shfl_xor_sync(0xffffffffu, s, 8);
            s += __shfl_xor_sync(0xffffffffu, s, 4);
            s += __shfl_xor_sync(0xffffffffu, s, 2);
            s += __shfl_xor_sync(0xffffffffu, s, 1);
            p[k] *= __fdividef(1.f, s);
        }
        float c = 0.f;
#pragma unroll
        for (int k = 0; k < NN; k++) c += p[k];
        float ci = (lane < NN) ? __fdividef(1.f, c) : 0.f;
#pragma unroll
        for (int k = 0; k < NN; k++) p[k] *= ci;
    }

    float* dst = out + (size_t)b * (NN * NN);
    if (lane < NN) {
#pragma unroll
        for (int k = 0; k < NN; k++) dst[k * NN + lane] = p[k];
    }
}

extern "C" void kernel_launch(void* const* d_in, const int* in_sizes, int n_in,
                              void* d_out, int out_size)
{
    const float* A      = (const float*)d_in[0];
    const float* m_     = (const float*)d_in[1];
    const float* tau_r  = (const float*)d_in[2];
    const float* ln1_g  = (const float*)d_in[3];
    const float* ln1_b  = (const float*)d_in[4];
    const float* W1     = (const float*)d_in[5];
    const float* b1     = (const float*)d_in[6];
    const float* W2     = (const float*)d_in[7];
    const float* b2     = (const float*)d_in[8];
    const float* ln2_g  = (const float*)d_in[9];
    const float* ln2_b  = (const float*)d_in[10];
    const float* protos = (const float*)d_in[11];

    int smCount = 148;
    cudaDeviceGetAttribute(&smCount, cudaDevAttrMultiProcessorCount, 0);
    cudaFuncSetAttribute((const void*)k1_scores,
                         cudaFuncAttributeMaxDynamicSharedMemorySize, SMEM_BYTES);

    k1_scores<<<smCount, 128, SMEM_BYTES>>>(A, m_, ln1_g, ln1_b, W1, b1,
                                            W2, b2, ln2_g, ln2_b, protos);
    k2_sinkhorn<<<(BB + 7) / 8, 256>>>(tau_r, (float*)d_out);
}

// round 9
// speedup vs baseline: 1.4344x; 1.1363x over previous
#include <cuda_runtime.h>
#include <math.h>

#define BB   32768
#define NQUAD 8192
#define NN   27
#define HID  128
#define SINK_ITERS 20

// Staging buffer for transposed scores: [b][k][n] (pre-tau, pre-exp).
__device__ float g_scores[(size_t)BB * NN * NN];

// ---------------- shared memory layout (floats) ----------------
#define OFF_W2   0          // 128*128
#define OFF_W1   16384      // 4*128
#define OFF_B1   16896
#define OFF_B2   17024
#define OFF_G2   17152
#define OFF_BB2  17280
#define OFF_LN1  17408      // 8
#define OFF_M    17416      // 108
#define OFF_P    17524      // 27*132 = 3564 ; stride 132 -> conflict-free LDS.128 spread
#define P_STRIDE 132
#define OFF_BAT  21088
// per-batch sub-offsets
#define BO_A 0               // 729 (pad 732)
#define BO_X 732             // 108 (pad 112)
#define BO_R 844             // 27*128
#define BO_H 4300            // 27*128
#define BO_SC 7756           // 27*29 = 783
#define PB   8540
#define SMEM_FLOATS (OFF_BAT + 4*PB)
#define SMEM_BYTES  (SMEM_FLOATS * 4)   // 220,992 B

// packed fp32x2 ops (bit-exact IEEE fp32 per component)
#define FFMA2ACC(d,a,b) asm("fma.rn.f32x2 %0, %1, %2, %0;" : "+l"(d) : "l"(a), "l"(b))
#define PADD(d,a,b)     asm("add.rn.f32x2 %0, %1, %2;" : "=l"(d) : "l"(a), "l"(b))
#define PMUL(d,a,b)     asm("mul.rn.f32x2 %0, %1, %2;" : "=l"(d) : "l"(a), "l"(b))

__device__ __forceinline__ unsigned long long dup2(float x) {
    unsigned long long r;
    asm("mov.b64 %0, {%1, %2};" : "=l"(r) : "f"(x), "f"(x));
    return r;
}
__device__ __forceinline__ unsigned long long pk2(float x, float y) {
    unsigned long long r;
    asm("mov.b64 %0, {%1, %2};" : "=l"(r) : "f"(x), "f"(y));
    return r;
}
__device__ __forceinline__ float2 unpk(unsigned long long v) {
    float2 f;
    asm("mov.b64 {%0, %1}, %2;" : "=f"(f.x), "=f"(f.y) : "l"(v));
    return f;
}
__device__ __forceinline__ float rcpa(float x) {
    float r;
    asm("rcp.approx.f32 %0, %1;" : "=f"(r) : "f"(x));
    return r;
}

// ---- P3: h = relu_r @ W2 + b2, NR rows (n = w2 + 2t), lane jq owns j=4jq..4jq+3 ----
template<int NR>
__device__ __forceinline__ void p3_rows(const float* __restrict__ srb,
                                        float* __restrict__ shb,
                                        const float* __restrict__ sW2,
                                        const float* __restrict__ sb2,
                                        int w2, int jq)
{
    const ulonglong2* W2v = (const ulonglong2*)sW2;
    unsigned long long aL[NR], aH[NR];
#pragma unroll
    for (int t = 0; t < NR; t++) { aL[t] = 0ull; aH[t] = 0ull; }
#pragma unroll 1
    for (int i = 0; i < HID; i += 4) {
        ulonglong2 w0 = W2v[(i + 0) * 32 + jq];
        ulonglong2 w1 = W2v[(i + 1) * 32 + jq];
        ulonglong2 w2v = W2v[(i + 2) * 32 + jq];
        ulonglong2 w3 = W2v[(i + 3) * 32 + jq];
#pragma unroll
        for (int t = 0; t < NR; t++) {
            const int n = w2 + 2 * t;
            float4 rq = *(const float4*)(srb + n * HID + i);     // broadcast LDS.128
            unsigned long long r0 = dup2(rq.x), r1 = dup2(rq.y);
            unsigned long long r2 = dup2(rq.z), r3 = dup2(rq.w);
            FFMA2ACC(aL[t], r0, w0.x);  FFMA2ACC(aH[t], r0, w0.y);
            FFMA2ACC(aL[t], r1, w1.x);  FFMA2ACC(aH[t], r1, w1.y);
            FFMA2ACC(aL[t], r2, w2v.x); FFMA2ACC(aH[t], r2, w2v.y);
            FFMA2ACC(aL[t], r3, w3.x);  FFMA2ACC(aH[t], r3, w3.y);
        }
    }
    float4 bb = ((const float4*)sb2)[jq];
#pragma unroll
    for (int t = 0; t < NR; t++) {
        const int n = w2 + 2 * t;
        float2 lo = unpk(aL[t]), hi = unpk(aH[t]);
        float4 o;
        o.x = lo.x + bb.x; o.y = lo.y + bb.y;
        o.z = hi.x + bb.z; o.w = hi.y + bb.w;
        *(float4*)(shb + n * HID + 4 * jq) = o;
    }
}

// ---- P5: scores[n][k] = H[n]·protos[k], lane = k, NR rows; store ssc[k][n] ----
template<int NR>
__device__ __forceinline__ void p5_rows(const float* __restrict__ shb,
                                        const float* __restrict__ sP,
                                        float* __restrict__ ssc,
                                        int w2, int k, bool kvalid)
{
    const int kk = kvalid ? k : (NN - 1);
    const ulonglong2* Pv = (const ulonglong2*)sP;    // row stride 132 fl = 33 ull2
    unsigned long long acc[NR];
#pragma unroll
    for (int t = 0; t < NR; t++) acc[t] = 0ull;
#pragma unroll 1
    for (int jq = 0; jq < 32; jq++) {
        ulonglong2 pv = Pv[kk * 33 + jq];            // conflict-free spread LDS.128
#pragma unroll
        for (int t = 0; t < NR; t++) {
            const int n = w2 + 2 * t;
            ulonglong2 hv = *(const ulonglong2*)(shb + n * HID + 4 * jq);  // broadcast
            FFMA2ACC(acc[t], hv.x, pv.x);
            FFMA2ACC(acc[t], hv.y, pv.y);
        }
    }
    if (kvalid) {
#pragma unroll
        for (int t = 0; t < NR; t++) {
            float2 s = unpk(acc[t]);
            ssc[k * 29 + (w2 + 2 * t)] = s.x + s.y;
        }
    }
}

__global__ void __launch_bounds__(256, 1)
k1_scores(const float* __restrict__ A,
          const float* __restrict__ m_,
          const float* __restrict__ ln1_g, const float* __restrict__ ln1_b,
          const float* __restrict__ W1,    const float* __restrict__ b1,
          const float* __restrict__ W2,    const float* __restrict__ b2,
          const float* __restrict__ ln2_g, const float* __restrict__ ln2_b,
          const float* __restrict__ protos)
{
    extern __shared__ float sm[];
    const int tid  = threadIdx.x;
    const int lane = tid & 31;
    const int q    = tid >> 6;          // which batch of the quad (0..3)
    const int htid = tid & 63;          // thread id within the 64-thread quarter
    const int w2   = (tid >> 5) & 1;    // warp within quarter: even/odd rows

    // ---- one-time parameter staging ----
    for (int i = tid; i < HID * HID; i += 256) sm[OFF_W2 + i] = W2[i];
    for (int i = tid; i < 4 * HID; i += 256)   sm[OFF_W1 + i] = W1[i];
    if (tid < HID) {
        sm[OFF_B1 + tid]  = b1[tid];
        sm[OFF_B2 + tid]  = b2[tid];
        sm[OFF_G2 + tid]  = ln2_g[tid];
        sm[OFF_BB2 + tid] = ln2_b[tid];
    }
    if (tid < 4) { sm[OFF_LN1 + tid] = ln1_g[tid]; sm[OFF_LN1 + 4 + tid] = ln1_b[tid]; }
    for (int i = tid; i < NN * HID; i += 256)
        sm[OFF_P + (i >> 7) * P_STRIDE + (i & 127)] = protos[i];
    __syncthreads();

    // static scatter map for A prefetch (idx -> (batch-in-quad, offset))
    int jj[12], oo[12];
#pragma unroll
    for (int u = 0; u < 12; u++) {
        int idx = tid + 256 * u;
        jj[u] = idx / (NN * NN);
        oo[u] = idx - jj[u] * (NN * NN);
    }

    // ---- software pipeline: prefetch A/m for the current quad into registers ----
    float pf[12];
    float mreg = 0.f;
    int bq = blockIdx.x;
    {
        const float* src = A + (size_t)bq * (4 * NN * NN);
#pragma unroll
        for (int u = 0; u < 12; u++) {
            int idx = tid + 256 * u;
            pf[u] = (idx < 4 * NN * NN) ? src[idx] : 0.f;
        }
        if (tid < 4 * NN) mreg = m_[(size_t)bq * 4 * NN + tid];
    }

    for (; bq < NQUAD; bq += (int)gridDim.x) {
#pragma unroll
        for (int u = 0; u < 12; u++) {
            int idx = tid + 256 * u;
            if (idx < 4 * NN * NN)
                sm[OFF_BAT + jj[u] * PB + BO_A + oo[u]] = pf[u];
        }
        if (tid < 4 * NN) sm[OFF_M + tid] = mreg;
        __syncthreads();

        // prefetch next quad while this one computes
        {
            int bqn = bq + (int)gridDim.x;
            if (bqn < NQUAD) {
                const float* src = A + (size_t)bqn * (4 * NN * NN);
#pragma unroll
                for (int u = 0; u < 12; u++) {
                    int idx = tid + 256 * u;
                    pf[u] = (idx < 4 * NN * NN) ? src[idx] : 0.f;
                }
                if (tid < 4 * NN) mreg = m_[(size_t)bqn * 4 * NN + tid];
            }
        }

        float* sB  = sm + OFF_BAT + q * PB;
        float* sA  = sB + BO_A;
        float* sx  = sB + BO_X;
        float* sr  = sB + BO_R;
        float* sh  = sB + BO_H;
        float* ssc = sB + BO_SC;

        // ---- P1: features + LN1 (27 threads per quarter) ----
        if (htid < NN) {
            const int n = htid;
            float s = 0.f, t1 = 0.f, t2 = 0.f;
#pragma unroll
            for (int j = 0; j < NN; j++) {
                float a = sA[n * NN + j];
                s += a;
                float v = (j == n) ? 0.0f : a;
                if (v > t1) { t2 = t1; t1 = v; }
                else if (v > t2) { t2 = v; }
            }
            float f0 = log1pf(s);
            float f3 = sm[OFF_M + q * NN + n];
            float mu = 0.25f * (f0 + t1 + t2 + f3);
            float d0 = f0 - mu, d1 = t1 - mu, d2 = t2 - mu, d3 = f3 - mu;
            float var = 0.25f * (d0 * d0 + d1 * d1 + d2 * d2 + d3 * d3);
            float rs = rsqrtf(var + 1e-5f);
            sx[n * 4 + 0] = d0 * rs * sm[OFF_LN1 + 0] + sm[OFF_LN1 + 4];
            sx[n * 4 + 1] = d1 * rs * sm[OFF_LN1 + 1] + sm[OFF_LN1 + 5];
            sx[n * 4 + 2] = d2 * rs * sm[OFF_LN1 + 2] + sm[OFF_LN1 + 6];
            sx[n * 4 + 3] = d3 * rs * sm[OFF_LN1 + 3] + sm[OFF_LN1 + 7];
        }
        __syncthreads();

        // ---- P2: r = relu(x @ W1 + b1) ----
        for (int idx = htid; idx < NN * HID; idx += 64) {
            int n = idx >> 7, j = idx & 127;
            float u = sm[OFF_B1 + j];
            u = fmaf(sx[n * 4 + 0], sm[OFF_W1 + 0 * HID + j], u);
            u = fmaf(sx[n * 4 + 1], sm[OFF_W1 + 1 * HID + j], u);
            u = fmaf(sx[n * 4 + 2], sm[OFF_W1 + 2 * HID + j], u);
            u = fmaf(sx[n * 4 + 3], sm[OFF_W1 + 3 * HID + j], u);
            sr[idx] = fmaxf(u, 0.f);
        }
        __syncthreads();

        // ---- P3: dominant GEMM in packed f32x2 ----
        if (w2 == 0) p3_rows<14>(sr, sh, sm + OFF_W2, sm + OFF_B2, 0, lane);
        else         p3_rows<13>(sr, sh, sm + OFF_W2, sm + OFF_B2, 1, lane);
        __syncthreads();

        // ---- P4: LayerNorm(128) per row (warp per row, even/odd split) ----
        for (int n = w2; n < NN; n += 2) {
            float4 v = ((float4*)sh)[n * 32 + lane];
            float s  = v.x + v.y + v.z + v.w;
            float s2 = v.x * v.x + v.y * v.y + v.z * v.z + v.w * v.w;
#pragma unroll
            for (int off = 16; off >= 1; off >>= 1) {
                s  += __shfl_xor_sync(0xffffffffu, s,  off);
                s2 += __shfl_xor_sync(0xffffffffu, s2, off);
            }
            float mu  = s  * (1.f / 128.f);
            float var = s2 * (1.f / 128.f) - mu * mu;
            float rs  = rsqrtf(var + 1e-5f);
            float4 g  = ((const float4*)(sm + OFF_G2))[lane];
            float4 be = ((const float4*)(sm + OFF_BB2))[lane];
            float4 o;
            o.x = (v.x - mu) * rs * g.x + be.x;
            o.y = (v.y - mu) * rs * g.y + be.y;
            o.z = (v.z - mu) * rs * g.z + be.z;
            o.w = (v.w - mu) * rs * g.w + be.w;
            ((float4*)sh)[n * 32 + lane] = o;
        }
        __syncthreads();

        // ---- P5: scores in packed f32x2, stored transposed [k][n] ----
        if (w2 == 0) p5_rows<14>(sh, sm + OFF_P, ssc, 0, lane, lane < NN);
        else         p5_rows<13>(sh, sm + OFF_P, ssc, 1, lane, lane < NN);
        __syncthreads();

        // ---- write transposed scores (coalesced) ----
        {
            float* dst = g_scores + (size_t)(4 * bq + q) * (NN * NN);
            for (int i = htid; i < NN * NN; i += 64) {
                int k = i / NN;
                int n = i - k * NN;
                dst[i] = ssc[k * 29 + n];
            }
        }
        __syncthreads();
    }
}

// ---------------- Sinkhorn: warp per TWO batches, packed f32x2 ----------------
// Lane = column n (lanes 27..31 hold zeros). p[k] holds (batch b0 | batch b1).
__global__ void __launch_bounds__(256)
k2_sinkhorn(const float* __restrict__ tau_r, float* __restrict__ out)
{
    const int warp = threadIdx.x >> 5;
    const int lane = threadIdx.x & 31;
    const int pi = blockIdx.x * 8 + warp;      // batch-pair index
    if (pi >= BB / 2) return;

    const float inv_tau = 1.0f / tau_r[0];
    const float* s0 = g_scores + (size_t)(2 * pi) * (NN * NN);
    const float* s1 = s0 + NN * NN;

    unsigned long long p[NN];
#pragma unroll
    for (int k = 0; k < NN; k++) {
        float v0 = 0.f, v1 = 0.f;
        if (lane < NN) {
            v0 = __expf(s0[k * NN + lane] * inv_tau);
            v1 = __expf(s1[k * NN + lane] * inv_tau);
        }
        p[k] = pk2(v0, v1);
    }

#pragma unroll 1
    for (int it = 0; it < SINK_ITERS; it++) {
        // row normalize: sum over n (across lanes)
#pragma unroll
        for (int k = 0; k < NN; k++) {
            unsigned long long s = p[k];
            unsigned long long t;
            t = __shfl_xor_sync(0xffffffffu, s, 16); PADD(s, s, t);
            t = __shfl_xor_sync(0xffffffffu, s, 8);  PADD(s, s, t);
            t = __shfl_xor_sync(0xffffffffu, s, 4);  PADD(s, s, t);
            t = __shfl_xor_sync(0xffffffffu, s, 2);  PADD(s, s, t);
            t = __shfl_xor_sync(0xffffffffu, s, 1);  PADD(s, s, t);
            float2 sv = unpk(s);
            unsigned long long inv = pk2(rcpa(sv.x), rcpa(sv.y));
            PMUL(p[k], p[k], inv);
        }
        // column normalize: sum over k (in-lane)
        unsigned long long c = p[0];
#pragma unroll
        for (int k = 1; k < NN; k++) PADD(c, c, p[k]);
        float2 cv = unpk(c);
        float cix = (lane < NN) ? rcpa(cv.x) : 0.f;   // keep dead lanes at 0
        float ciy = (lane < NN) ? rcpa(cv.y) : 0.f;
        unsigned long long ci = pk2(cix, ciy);
#pragma unroll
        for (int k = 0; k < NN; k++) PMUL(p[k], p[k], ci);
    }

    if (lane < NN) {
        float* d0 = out + (size_t)(2 * pi) * (NN * NN);
        float* d1 = d0 + NN * NN;
#pragma unroll
        for (int k = 0; k < NN; k++) {
            float2 v = unpk(p[k]);
            d0[k * NN + lane] = v.x;
            d1[k * NN + lane] = v.y;
        }
    }
}

extern "C" void kernel_launch(void* const* d_in, const int* in_sizes, int n_in,
                              void* d_out, int out_size)
{
    const float* A      = (const float*)d_in[0];
    const float* m_     = (const float*)d_in[1];
    const float* tau_r  = (const float*)d_in[2];
    const float* ln1_g  = (const float*)d_in[3];
    const float* ln1_b  = (const float*)d_in[4];
    const float* W1     = (const float*)d_in[5];
    const float* b1     = (const float*)d_in[6];
    const float* W2     = (const float*)d_in[7];
    const float* b2     = (const float*)d_in[8];
    const float* ln2_g  = (const float*)d_in[9];
    const float* ln2_b  = (const float*)d_in[10];
    const float* protos = (const float*)d_in[11];

    int smCount = 148;
    cudaDeviceGetAttribute(&smCount, cudaDevAttrMultiProcessorCount, 0);
    cudaFuncSetAttribute((const void*)k1_scores,
                         cudaFuncAttributeMaxDynamicSharedMemorySize, SMEM_BYTES);

    k1_scores<<<smCount, 256, SMEM_BYTES>>>(A, m_, ln1_g, ln1_b, W1, b1,
                                            W2, b2, ln2_g, ln2_b, protos);
    k2_sinkhorn<<<(BB / 2 + 7) / 8, 256>>>(tau_r, (float*)d_out);
}